// round 16
// baseline (speedup 1.0000x reference)
#include <cuda_runtime.h>
#include <cstdint>

// BinLinear: out = input @ sign(tanh(weight)), weight_b in {-1,+1}.
// Identity: out[n,o] = S[n] - 2*T[n,o], S[n]=rowsum(input row n),
//           T[n,o]  = sum of x[n,k] over k where weight[k,o] < 0.
// Exact fp32 products; only summation order differs from reference.
//
// R16: inverted PDL roles. PRIMARY = binarize (512 blocks, 16MB, triggers
// launch completion at the top). SECONDARY = rowfill-all (1024 blocks,
// warp-per-row): read row -> S -> STORE ROW (before the sync, preserving
// store pipelining), then cudaGridDependencySynchronize() (binarize long
// finished -> satisfied wait), read g_anyflag, exit on the fast path.
// General path: the same thread that stored a quad overwrites its affected
// elements (same-address program order, no fences). Both grids co-resident
// from t~0 => full 144.5MB streams at the measured ~6.4TB/s cap with one
// effective launch ramp and a hardware-tracked dependency.
//
// Shapes fixed: M=8192, K=2048 (num_ip), N=2048 (num_op).

#define MDIM 8192
#define KDIM 2048
#define NDIM 2048
#define NQ   (NDIM / 4)      // 512 column quads
#define KB   (KDIM / 8)      // 256 k-groups of 8 (32-bit mask words)
#define FULL 0xffffffffu

#define BIN_BLOCKS 512
#define RF_BLOCKS  1024

// Scratch (no cudaMalloc). Zero-initialized; mask writes value-identical
// across replays, OR-atomics idempotent -> replay-deterministic.
// g_mask[kb*NQ + c4]: bit (j*4+e) = sign of weight[kb*8+j][c4*4+e] (1 => -1).
__device__ uint32_t g_mask[KB * NQ];     // 512 KB
__device__ uint32_t g_negq[NQ];          // per-quad OR of mask words (rare path)
__device__ uint32_t g_anyflag;           // nonzero iff any negative weight

// ---------------------------------------------------------------------------
// PRIMARY: binarize. Thread owns (quad c4, 8 k's): 8 independent coalesced
// LDG.128, pack 32 sign bits, one coalesced word store (+ idempotent
// atomics only when negatives exist). Triggers PDL completion immediately
// so the rowfill grid co-schedules from the start.
// ---------------------------------------------------------------------------
__global__ void __launch_bounds__(256) binarize_kernel(const float4* __restrict__ w4) {
    cudaTriggerProgrammaticLaunchCompletion();

    int tid = blockIdx.x * 256 + threadIdx.x;        // 0..131071
    int c4  = tid & (NQ - 1);                        // fastest -> coalesced
    int kb  = tid >> 9;                              // 0..255
    const float4* base = w4 + (size_t)(kb * 8) * NQ + c4;

    uint32_t bits = 0;
    #pragma unroll
    for (int j = 0; j < 8; j++) {
        float4 v = __ldcs(&base[(size_t)j * NQ]);
        uint32_t b = (uint32_t)(v.x < 0.0f)
                   | ((uint32_t)(v.y < 0.0f) << 1)
                   | ((uint32_t)(v.z < 0.0f) << 2)
                   | ((uint32_t)(v.w < 0.0f) << 3);
        bits |= b << (j * 4);
    }
    g_mask[kb * NQ + c4] = bits;                     // coalesced word store

    if (bits) {                                      // rare path (idempotent)
        atomicOr(&g_negq[c4], bits);
        atomicOr(&g_anyflag, 1u);
    }
}

// ---------------------------------------------------------------------------
// SECONDARY (PDL): rowfill-all. One warp per row.
// Preamble: 16 evict-first LDG.128 -> shuffle reduce -> 16 plain STG.128.
// Then gridsync (binarize complete + visible), flag check, and — only if
// negatives exist — exact per-column corrections by the owning thread.
// ---------------------------------------------------------------------------
__global__ void __launch_bounds__(256) rowfill_kernel(const float* __restrict__ x,
                                                      float* __restrict__ out) {
    int lane = threadIdx.x & 31;
    int row  = blockIdx.x * 8 + (threadIdx.x >> 5);
    const float4* xrow4 = (const float4*)(x + (size_t)row * KDIM);

    float s = 0.0f;
    #pragma unroll
    for (int half = 0; half < 2; half++) {           // 2 batches of 8 in flight
        float4 v[8];
        #pragma unroll
        for (int i = 0; i < 8; i++)
            v[i] = __ldcs(&xrow4[lane + 32 * (half * 8 + i)]);
        #pragma unroll
        for (int i = 0; i < 8; i++)
            s += (v[i].x + v[i].y) + (v[i].z + v[i].w);
    }
    #pragma unroll
    for (int ofs = 16; ofs; ofs >>= 1)
        s += __shfl_xor_sync(FULL, s, ofs);          // all lanes hold S

    // Store phase BEFORE the dependency sync: pipelining preserved.
    float4* orow4 = (float4*)(out + (size_t)row * NDIM);
    float4 val = make_float4(s, s, s, s);
    #pragma unroll
    for (int i = 0; i < 16; i++)
        orow4[lane + 32 * i] = val;                  // plain stores -> L2

    // Hardware-tracked wait: binarize (finished long ago) + memory flush.
    cudaGridDependencySynchronize();
    if (g_anyflag == 0) return;                      // dataset case: done

    // General path (absent on this dataset, kept exact): the SAME thread
    // that stored a quad overwrites its affected elements -> per-address
    // program order within the thread, no fences needed.
    const float* xrow = x + (size_t)row * KDIM;
    #pragma unroll 1
    for (int i = 0; i < 16; i++) {
        int c4 = lane + 32 * i;                      // columns c4*4..c4*4+3
        uint32_t q = g_negq[c4];
        if (!q) continue;
        #pragma unroll 1
        for (int e = 0; e < 4; e++) {
            if ((q >> e) & 0x11111111u) {
                float T = 0.0f;
                for (int kb = 0; kb < KB; kb++) {
                    uint32_t word = g_mask[kb * NQ + c4];
                    uint32_t sel = (word >> e) & 0x11111111u;
                    while (sel) {
                        int b = __ffs(sel) - 1;      // b = j*4
                        sel &= sel - 1;
                        T += xrow[kb * 8 + (b >> 2)];
                    }
                }
                out[(size_t)row * NDIM + c4 * 4 + e] = s - 2.0f * T;
            }
        }
    }
}

extern "C" void kernel_launch(void* const* d_in, const int* in_sizes, int n_in,
                              void* d_out, int out_size) {
    const float* input  = (const float*)d_in[0];   // [8192, 2048]
    const float* weight = (const float*)d_in[1];   // [2048, 2048]
    float* out = (float*)d_out;                    // [8192, 2048]

    binarize_kernel<<<BIN_BLOCKS, 256>>>((const float4*)weight);

    // Rowfill as PDL secondary: co-schedules with binarize immediately;
    // its gridsync orders the (rare) correction path after binarize.
    cudaLaunchConfig_t cfg = {};
    cfg.gridDim  = dim3(RF_BLOCKS, 1, 1);
    cfg.blockDim = dim3(256, 1, 1);
    cfg.dynamicSmemBytes = 0;
    cudaLaunchAttribute attrs[1];
    attrs[0].id = cudaLaunchAttributeProgrammaticStreamSerialization;
    attrs[0].val.programmaticStreamSerializationAllowed = 1;
    cfg.attrs = attrs;
    cfg.numAttrs = 1;
    cudaLaunchKernelEx(&cfg, rowfill_kernel, input, out);
}

// round 17
// speedup vs baseline: 1.0368x; 1.0368x over previous
#include <cuda_runtime.h>
#include <cstdint>

// BinLinear: out = input @ sign(tanh(weight)), weight_b in {-1,+1}.
// Identity: out[n,o] = S[n] - 2*T[n,o], S[n]=rowsum(input row n),
//           T[n,o]  = sum of x[n,k] over k where weight[k,o] < 0.
// Exact fp32 products; only summation order differs from reference.
//
// R17 = R14 (best: 26.6us) with exactly ONE change: the PDL trigger moves
// from the END of mega to the TOP. R14's fixup exposure was ~4us because
// the secondary couldn't even begin its launch/ramp until mega blocks
// retired; with the trigger first, fixup's 64 blocks launch during mega,
// park at the hardware gridsync (no memory traffic, ~4% of block slots),
// and wake to a one-flag-read fast exit. Memory ordering is unchanged:
// cudaGridDependencySynchronize waits for FULL primary completion + flush
// regardless of trigger placement.
//
// Shapes fixed: M=8192, K=2048 (num_ip), N=2048 (num_op).

#define MDIM 8192
#define KDIM 2048
#define NDIM 2048
#define NQ   (NDIM / 4)      // 512 column quads
#define KB   (KDIM / 8)      // 256 k-groups of 8 (32-bit mask words)
#define FULL 0xffffffffu
#define FIX_BLOCKS 64

// Scratch (no cudaMalloc). Zero-initialized; mask writes value-identical
// across replays, OR-atomics idempotent -> replay-deterministic.
// g_mask[kb*NQ + c4]: bit (j*4+e) = sign of weight[kb*8+j][c4*4+e] (1 => -1).
__device__ uint32_t g_mask[KB * NQ];     // 512 KB
__device__ uint32_t g_negq[NQ];          // per-quad OR of mask words (rare path)
__device__ uint32_t g_anyflag;           // nonzero iff any negative weight
__device__ float    g_S[MDIM];           // row sums (read by fixup)

// ---------------------------------------------------------------------------
// Mega kernel (hot path identical to R10/R14's measured 22.6us version):
// 1536 blocks, roles interleaved 2:1.
//   bid%3 < 2  -> rowfill (8 warps, warp-per-row): 16 evict-first LDG.128 ->
//                 shuffle reduce -> S -> store g_S -> 16 plain STG.128.
//   bid%3 == 2 -> binarize: thread owns (quad c4, 8 k's): 8 evict-first
//                 LDG.128, pack 32 sign bits, 1 word store (+ idempotent
//                 atomics only if negatives exist).
// ---------------------------------------------------------------------------
__global__ void __launch_bounds__(256) mega_kernel(const float4* __restrict__ w4,
                                                   const float* __restrict__ x,
                                                   float* __restrict__ out) {
    cudaTriggerProgrammaticLaunchCompletion();       // FIRST: let fixup ramp now

    int bid = blockIdx.x;
    int g = bid / 3;
    int rem = bid - g * 3;

    if (rem < 2) {
        // ---- rowfill: one-pass read row -> S -> write row ----
        int rb   = g * 2 + rem;                      // 0..1023
        int row  = rb * 8 + (threadIdx.x >> 5);
        int lane = threadIdx.x & 31;
        const float4* xrow4 = (const float4*)(x + (size_t)row * KDIM);

        float s = 0.0f;
        #pragma unroll
        for (int half = 0; half < 2; half++) {       // 2 batches of 8 in flight
            float4 v[8];
            #pragma unroll
            for (int i = 0; i < 8; i++)
                v[i] = __ldcs(&xrow4[lane + 32 * (half * 8 + i)]);
            #pragma unroll
            for (int i = 0; i < 8; i++)
                s += (v[i].x + v[i].y) + (v[i].z + v[i].w);
        }
        #pragma unroll
        for (int ofs = 16; ofs; ofs >>= 1)
            s += __shfl_xor_sync(FULL, s, ofs);      // all lanes hold S
        if (lane == 0) g_S[row] = s;

        float4 val = make_float4(s, s, s, s);
        float4* orow4 = (float4*)(out + (size_t)row * NDIM);
        #pragma unroll
        for (int i = 0; i < 16; i++)
            orow4[lane + 32 * i] = val;              // plain stores -> L2
    } else {
        // ---- binarize: thread owns (c4, 8 k's) ----
        int tid = g * 256 + threadIdx.x;             // 0..131071
        int c4  = tid & (NQ - 1);                    // fastest -> coalesced
        int kb  = tid >> 9;                          // 0..255
        const float4* base = w4 + (size_t)(kb * 8) * NQ + c4;

        uint32_t bits = 0;
        #pragma unroll
        for (int j = 0; j < 8; j++) {
            float4 v = __ldcs(&base[(size_t)j * NQ]);
            uint32_t b = (uint32_t)(v.x < 0.0f)
                       | ((uint32_t)(v.y < 0.0f) << 1)
                       | ((uint32_t)(v.z < 0.0f) << 2)
                       | ((uint32_t)(v.w < 0.0f) << 3);
            bits |= b << (j * 4);
        }
        g_mask[kb * NQ + c4] = bits;                 // coalesced word store

        if (bits) {                                  // rare path (idempotent)
            atomicOr(&g_negq[c4], bits);
            atomicOr(&g_anyflag, 1u);
        }
    }
}

// ---------------------------------------------------------------------------
// Fixup (PDL secondary): launches during mega, parks at the gridsync, wakes
// to a one-flag-read exit when no negative weights exist (dataset case).
// General case: strides over column quads; overwrites affected elements
// with the exact S[n] - 2*T[n,c] recomputed from input + mask (pure
// overwrite, no RMW -> deterministic).
// ---------------------------------------------------------------------------
__global__ void __launch_bounds__(256) fixup_kernel(const float* __restrict__ x,
                                                    float* __restrict__ out) {
    cudaGridDependencySynchronize();                 // mega complete + visible

    if (g_anyflag == 0) return;                      // broadcast, L2-hot

    for (int c4 = blockIdx.x; c4 < NQ; c4 += FIX_BLOCKS) {
        uint32_t q = g_negq[c4];
        if (q == 0) continue;
        for (int n = threadIdx.x; n < MDIM; n += 256) {
            const float* xrow = x + (size_t)n * KDIM;
            float s = g_S[n];
            #pragma unroll
            for (int e = 0; e < 4; e++) {
                if ((q >> e) & 0x11111111u) {
                    float T = 0.0f;
                    for (int kb = 0; kb < KB; kb++) {
                        uint32_t word = g_mask[kb * NQ + c4];
                        uint32_t sel = (word >> e) & 0x11111111u;
                        while (sel) {
                            int b = __ffs(sel) - 1;  // b = j*4
                            sel &= sel - 1;
                            T += xrow[kb * 8 + (b >> 2)];
                        }
                    }
                    out[(size_t)n * NDIM + c4 * 4 + e] = s - 2.0f * T;
                }
            }
        }
    }
}

extern "C" void kernel_launch(void* const* d_in, const int* in_sizes, int n_in,
                              void* d_out, int out_size) {
    const float* input  = (const float*)d_in[0];   // [8192, 2048]
    const float* weight = (const float*)d_in[1];   // [2048, 2048]
    float* out = (float*)d_out;                    // [8192, 2048]

    mega_kernel<<<1536, 256>>>((const float4*)weight, input, out);

    // Fixup with Programmatic Dependent Launch: ramp overlaps mega.
    cudaLaunchConfig_t cfg = {};
    cfg.gridDim  = dim3(FIX_BLOCKS, 1, 1);
    cfg.blockDim = dim3(256, 1, 1);
    cfg.dynamicSmemBytes = 0;
    cudaLaunchAttribute attrs[1];
    attrs[0].id = cudaLaunchAttributeProgrammaticStreamSerialization;
    attrs[0].val.programmaticStreamSerializationAllowed = 1;
    cfg.attrs = attrs;
    cfg.numAttrs = 1;
    cudaLaunchKernelEx(&cfg, fixup_kernel, input, out);
}